// round 6
// baseline (speedup 1.0000x reference)
#include <cuda_runtime.h>
#include <cuda_bf16.h>

// Problem constants
#define BATCH 8
#define SEQ   8192
#define DMODEL 1024
#define NTOK (BATCH * SEQ)

// Scratch: sortable keys per token (monotone uint transform of masked score)
__device__ unsigned int g_keys[NTOK];

// ---------------------------------------------------------------------------
// Kernel 1: scores[b,s] = dot(hidden[b,s,:], w) + bias ; key = sortable(score)
// One warp per token. Each lane reads 8 float4 (strided), warp tree-reduce.
// HBM-bound: streams 256 MB of hidden once.
// mask elements are 4 bytes (float32 1.0/0.0 from the harness bool->f32
// promotion; a bit-level nonzero test also covers int32 1/0).
// ---------------------------------------------------------------------------
__global__ void __launch_bounds__(256)
score_kernel(const float* __restrict__ hidden,
             const unsigned int* __restrict__ mask,
             const float* __restrict__ w,
             const float* __restrict__ bias)
{
    int warp = (blockIdx.x * blockDim.x + threadIdx.x) >> 5;
    int lane = threadIdx.x & 31;
    if (warp >= NTOK) return;

    const float4* hp = reinterpret_cast<const float4*>(hidden + (size_t)warp * DMODEL);
    const float4* wp = reinterpret_cast<const float4*>(w);

    float acc = 0.0f;
#pragma unroll
    for (int i = 0; i < 8; i++) {
        float4 a = hp[lane + i * 32];
        float4 c = wp[lane + i * 32];
        acc += a.x * c.x + a.y * c.y + a.z * c.z + a.w * c.w;
    }
#pragma unroll
    for (int o = 16; o; o >>= 1) acc += __shfl_xor_sync(0xFFFFFFFFu, acc, o);

    if (lane == 0) {
        float s = acc + bias[0];
        unsigned int u = __float_as_uint(s);
        // order-preserving map: larger float -> larger uint
        u = (u & 0x80000000u) ? ~u : (u | 0x80000000u);
        // inactive -> 0 (strictly below any active key: all finite/-inf
        // scores map to > 0)
        g_keys[warp] = (mask[warp] != 0u) ? u : 0u;
    }
}

// ---------------------------------------------------------------------------
// Kernel 2: per-row exact top-k with stable (lowest-index-first) tie break.
// One block per row. Keys resident in SMEM (32 KB). 4-pass MSB radix select
// finds the k-th largest key t; then keep (key > t) plus the first
// (k - count_gt) tokens with key == t, ordered by index (binary search cutoff).
// ---------------------------------------------------------------------------
__device__ __forceinline__ int block_reduce_int(int v, int* red)
{
    int lane = threadIdx.x & 31, wid = threadIdx.x >> 5;
#pragma unroll
    for (int o = 16; o; o >>= 1) v += __shfl_xor_sync(0xFFFFFFFFu, v, o);
    if (lane == 0) red[wid] = v;
    __syncthreads();
    if (wid == 0) {
        int x = (lane < (int)(blockDim.x >> 5)) ? red[lane] : 0;
#pragma unroll
        for (int o = 16; o; o >>= 1) x += __shfl_xor_sync(0xFFFFFFFFu, x, o);
        if (lane == 0) red[0] = x;
    }
    __syncthreads();
    int r = red[0];
    __syncthreads();   // protect red[] before next reuse
    return r;
}

__global__ void __launch_bounds__(1024)
select_kernel(const unsigned int* __restrict__ mask,
              float* __restrict__ out)
{
    __shared__ unsigned int skeys[SEQ];   // 32 KB
    __shared__ int hist[256];
    __shared__ int red[32];
    __shared__ int bcast[2];

    const int b   = blockIdx.x;
    const int tid = threadIdx.x;
    const unsigned int* keys = g_keys + b * SEQ;
    const unsigned int* m    = mask + b * SEQ;
    float* o                 = out + b * SEQ;

    // Load keys, count active
    int na = 0;
    for (int i = tid; i < SEQ; i += 1024) {
        unsigned int kk = keys[i];
        skeys[i] = kk;
        na += (m[i] != 0u) ? 1 : 0;
    }
    __syncthreads();
    int n_active = block_reduce_int(na, red);

    if (n_active == 0) {
        for (int i = tid; i < SEQ; i += 1024) o[i] = 0.0f;
        return;
    }
    const int k = (n_active + 1) >> 1;   // max(1, ceil(0.5*n)) for n>=1

    // MSB-first radix select: find k-th largest key value t
    unsigned int prefix = 0;
    int krem = k;
#pragma unroll
    for (int shift = 24; shift >= 0; shift -= 8) {
        for (int i = tid; i < 256; i += 1024) hist[i] = 0;
        __syncthreads();
        unsigned int pmask = (shift == 24) ? 0u : (0xFFFFFFFFu << (shift + 8));
        for (int i = tid; i < SEQ; i += 1024) {
            unsigned int v = skeys[i];
            if ((v & pmask) == prefix)
                atomicAdd(&hist[(v >> shift) & 255], 1);
        }
        __syncthreads();
        if (tid == 0) {
            int rem = krem, bin = 255;
            for (; bin > 0; bin--) {
                int c = hist[bin];
                if (rem <= c) break;
                rem -= c;
            }
            bcast[0] = bin;
            bcast[1] = rem;
        }
        __syncthreads();
        prefix |= ((unsigned int)bcast[0]) << shift;
        krem = bcast[1];
        __syncthreads();
    }
    const unsigned int t = prefix;

    // Count strictly-greater and equal
    int cgt = 0, ceq = 0;
    for (int i = tid; i < SEQ; i += 1024) {
        unsigned int v = skeys[i];
        cgt += (v > t) ? 1 : 0;
        ceq += (v == t) ? 1 : 0;
    }
    int count_gt = block_reduce_int(cgt, red);
    int count_eq = block_reduce_int(ceq, red);
    int mneed = k - count_gt;   // >= 1 equals to admit, lowest-index first

    // Index cutoff: smallest c with #(equals, idx<=c) >= mneed
    int cut = SEQ - 1;
    if (mneed < count_eq) {
        int lo = 0, hi = SEQ - 1;
        while (lo < hi) {
            int mid = (lo + hi) >> 1;
            int cnt = 0;
            for (int i = tid; i <= mid; i += 1024)
                cnt += (skeys[i] == t) ? 1 : 0;
            int tot = block_reduce_int(cnt, red);
            if (tot >= mneed) hi = mid; else lo = mid + 1;
        }
        cut = lo;
    }

    // Emit keep mask as float 1.0/0.0 (bool output promoted to f32)
    for (int i = tid; i < SEQ; i += 1024) {
        unsigned int v = skeys[i];
        bool keep = (v > t) || (v == t && i <= cut);
        o[i] = ((m[i] != 0u) && keep) ? 1.0f : 0.0f;
    }
}

extern "C" void kernel_launch(void* const* d_in, const int* in_sizes, int n_in,
                              void* d_out, int out_size)
{
    // Bind inputs by element count (all four are distinct sizes) so no
    // ordering assumption can break us:
    //   hidden: 8*8192*1024 = 67108864, mask: 65536, w: 1024, b: 1
    const float*        hidden = nullptr;
    const unsigned int* mask   = nullptr;
    const float*        w      = nullptr;
    const float*        bias   = nullptr;
    for (int i = 0; i < n_in; i++) {
        switch (in_sizes[i]) {
            case NTOK * DMODEL / 1: break; // placeholder (avoid warnings)
        }
        if (in_sizes[i] == 67108864)      hidden = (const float*)d_in[i];
        else if (in_sizes[i] == 65536)    mask   = (const unsigned int*)d_in[i];
        else if (in_sizes[i] == 1024)     w      = (const float*)d_in[i];
        else if (in_sizes[i] == 1)        bias   = (const float*)d_in[i];
    }
    float* out = (float*)d_out;

    // 1 warp/token, 8 warps/block -> NTOK/8 blocks
    score_kernel<<<NTOK / 8, 256>>>(hidden, mask, w, bias);
    select_kernel<<<BATCH, 1024>>>(mask, out);
}

// round 7
// speedup vs baseline: 1.2199x; 1.2199x over previous
#include <cuda_runtime.h>
#include <cuda_bf16.h>

#define BATCH 8
#define SEQ   8192
#define DMODEL 1024
#define NTOK (BATCH * SEQ)
#define FULL 0xFFFFFFFFu

// Scratch: sortable keys per token. Active key = monotone uint transform of
// score (always > 0); inactive = 0. So select needs only this array.
__device__ unsigned int g_keys[NTOK];

// ---------------------------------------------------------------------------
// Kernel 1: scores[b,s] = dot(hidden[b,s,:], w) + bias ; key = sortable(score)
// One warp per token; streams 256 MB of hidden once. HBM-bound (~6.2 TB/s).
// ---------------------------------------------------------------------------
__global__ void __launch_bounds__(256)
score_kernel(const float* __restrict__ hidden,
             const unsigned int* __restrict__ mask,
             const float* __restrict__ w,
             const float* __restrict__ bias)
{
    int warp = (blockIdx.x * blockDim.x + threadIdx.x) >> 5;
    int lane = threadIdx.x & 31;
    if (warp >= NTOK) return;

    const float4* hp = reinterpret_cast<const float4*>(hidden + (size_t)warp * DMODEL);
    const float4* wp = reinterpret_cast<const float4*>(w);

    float acc = 0.0f;
#pragma unroll
    for (int i = 0; i < 8; i++) {
        float4 a = hp[lane + i * 32];
        float4 c = wp[lane + i * 32];
        acc += a.x * c.x + a.y * c.y + a.z * c.z + a.w * c.w;
    }
#pragma unroll
    for (int o = 16; o; o >>= 1) acc += __shfl_xor_sync(FULL, acc, o);

    if (lane == 0) {
        float s = acc + bias[0];
        unsigned int u = __float_as_uint(s);
        u = (u & 0x80000000u) ? ~u : (u | 0x80000000u);  // order-preserving
        g_keys[warp] = (mask[warp] != 0u) ? u : 0u;      // inactive -> 0
    }
}

// ---------------------------------------------------------------------------
// Kernel 2: per-row exact variable top-k, stable lowest-index tie break.
// One block/row, 1024 threads, each owns 8 CONTIGUOUS keys in registers.
// 4-pass MSB radix select with warp-aggregated histogram atomics and a
// parallel suffix scan over the 256 bins (no serial tid==0 loop, no binary
// search). Tie-break via one exclusive block scan of equal-counts.
// ---------------------------------------------------------------------------
__device__ __forceinline__ int block_reduce_int(int v, int* red)
{
    int lane = threadIdx.x & 31, wid = threadIdx.x >> 5;
#pragma unroll
    for (int o = 16; o; o >>= 1) v += __shfl_xor_sync(FULL, v, o);
    if (lane == 0) red[wid] = v;
    __syncthreads();
    if (wid == 0) {
        int x = (lane < 32) ? red[lane] : 0;
#pragma unroll
        for (int o = 16; o; o >>= 1) x += __shfl_xor_sync(FULL, x, o);
        if (lane == 0) red[0] = x;
    }
    __syncthreads();
    int r = red[0];
    __syncthreads();
    return r;
}

__global__ void __launch_bounds__(1024)
select_kernel(float* __restrict__ out)
{
    __shared__ int hist[256];
    __shared__ int sfx[257];      // suffix sums; sfx[256] = 0 sentinel
    __shared__ int wsum[32];
    __shared__ int red[32];
    __shared__ int bcast[2];

    const int b = blockIdx.x, tid = threadIdx.x;
    const int lane = tid & 31, wid = tid >> 5;
    const unsigned int* keys = g_keys + b * SEQ;
    float* o = out + b * SEQ;

    // Each thread owns contiguous indices [tid*8, tid*8+8)
    const uint4 k0 = reinterpret_cast<const uint4*>(keys)[tid * 2];
    const uint4 k1 = reinterpret_cast<const uint4*>(keys)[tid * 2 + 1];
    unsigned int v[8] = {k0.x, k0.y, k0.z, k0.w, k1.x, k1.y, k1.z, k1.w};

    // n_active = count(key != 0)
    int na = 0;
#pragma unroll
    for (int i = 0; i < 8; i++) na += (v[i] != 0u);
    const int n_active = block_reduce_int(na, red);

    if (n_active == 0) {
        float4 z = make_float4(0.f, 0.f, 0.f, 0.f);
        reinterpret_cast<float4*>(o)[tid * 2]     = z;
        reinterpret_cast<float4*>(o)[tid * 2 + 1] = z;
        return;
    }
    const int k = (n_active + 1) >> 1;   // max(1, ceil(n/2)) for n >= 1

    // ---- MSB-first radix select for the k-th largest key t ----
    unsigned int prefix = 0;
    int krem = k;
#pragma unroll
    for (int shift = 24; shift >= 0; shift -= 8) {
        if (tid < 256) hist[tid] = 0;
        if (tid == 256) sfx[256] = 0;
        __syncthreads();

        const unsigned int pmask = (shift == 24) ? 0u : (FULL << (shift + 8));
#pragma unroll
        for (int i = 0; i < 8; i++) {
            bool p = (v[i] & pmask) == prefix;
            unsigned int bin = (v[i] >> shift) & 255u;
            unsigned int tag = p ? bin : 0x100u;           // sentinel for non-participants
            unsigned int peers = __match_any_sync(FULL, tag);
            if (p && ((int)(__ffs(peers) - 1) == lane))
                atomicAdd(&hist[bin], __popc(peers));      // one atomic per group
        }
        __syncthreads();

        // Parallel suffix scan: sfx[bin] = sum_{j>=bin} hist[j]
        // thread t handles bin 255-t; inclusive prefix over t == suffix over bin.
        int sval = 0;
        if (tid < 256) {
            sval = hist[255 - tid];
#pragma unroll
            for (int d = 1; d < 32; d <<= 1) {
                int n2 = __shfl_up_sync(FULL, sval, d);
                if (lane >= d) sval += n2;
            }
            if (lane == 31) wsum[wid] = sval;   // wid in 0..7
        }
        __syncthreads();
        if (tid < 8) {
            int x = wsum[tid];
#pragma unroll
            for (int d = 1; d < 8; d <<= 1) {
                int n2 = __shfl_up_sync(0xFFu, x, d);
                if (tid >= d) x += n2;
            }
            wsum[tid] = x;                      // inclusive warp-sum scan
        }
        __syncthreads();
        if (tid < 256) {
            int total = sval + ((wid > 0) ? wsum[wid - 1] : 0);
            sfx[255 - tid] = total;
        }
        __syncthreads();
        if (tid < 256) {
            int bin = 255 - tid;
            int S = sfx[bin], Sn = sfx[bin + 1];
            if (S >= krem && Sn < krem) {       // unique boundary (S monotone)
                bcast[0] = bin;
                bcast[1] = krem - Sn;
            }
        }
        __syncthreads();
        prefix |= ((unsigned int)bcast[0]) << shift;
        krem = bcast[1];
        __syncthreads();
    }
    const unsigned int t = prefix;

    // ---- count strictly greater -> how many equals to admit ----
    int cgt = 0;
#pragma unroll
    for (int i = 0; i < 8; i++) cgt += (v[i] > t);
    const int count_gt = block_reduce_int(cgt, red);
    const int mneed = k - count_gt;             // >= 1

    // ---- stable rank among equals: exclusive block scan over thread-local
    //      equal counts (thread order == index order, contiguity) ----
    int le = 0;
#pragma unroll
    for (int i = 0; i < 8; i++) le += (v[i] == t);
    int s = le;
#pragma unroll
    for (int d = 1; d < 32; d <<= 1) {
        int n2 = __shfl_up_sync(FULL, s, d);
        if (lane >= d) s += n2;
    }
    if (lane == 31) wsum[wid] = s;
    __syncthreads();
    if (wid == 0) {
        int x = wsum[lane];
#pragma unroll
        for (int d = 1; d < 32; d <<= 1) {
            int n2 = __shfl_up_sync(FULL, x, d);
            if (lane >= d) x += n2;
        }
        wsum[lane] = x;                         // inclusive
    }
    __syncthreads();
    int eq_rank = s - le + ((wid > 0) ? wsum[wid - 1] : 0);  // exclusive global rank

    // ---- emit keep mask as float 1.0/0.0 ----
    float r8[8];
#pragma unroll
    for (int i = 0; i < 8; i++) {
        bool keep;
        if (v[i] > t)       keep = true;
        else if (v[i] == t) { keep = (eq_rank < mneed); eq_rank++; }
        else                keep = false;
        r8[i] = keep ? 1.0f : 0.0f;
    }
    reinterpret_cast<float4*>(o)[tid * 2]     = make_float4(r8[0], r8[1], r8[2], r8[3]);
    reinterpret_cast<float4*>(o)[tid * 2 + 1] = make_float4(r8[4], r8[5], r8[6], r8[7]);
}

extern "C" void kernel_launch(void* const* d_in, const int* in_sizes, int n_in,
                              void* d_out, int out_size)
{
    // Bind inputs by element count (all distinct):
    //   hidden 67108864, mask 65536, w 1024, bias 1
    const float*        hidden = nullptr;
    const unsigned int* mask   = nullptr;
    const float*        w      = nullptr;
    const float*        bias   = nullptr;
    for (int i = 0; i < n_in; i++) {
        if      (in_sizes[i] == 67108864) hidden = (const float*)d_in[i];
        else if (in_sizes[i] == 65536)    mask   = (const unsigned int*)d_in[i];
        else if (in_sizes[i] == 1024)     w      = (const float*)d_in[i];
        else if (in_sizes[i] == 1)        bias   = (const float*)d_in[i];
    }
    float* out = (float*)d_out;

    score_kernel<<<NTOK / 8, 256>>>(hidden, mask, w, bias);
    select_kernel<<<BATCH, 1024>>>(out);
}